// round 1
// baseline (speedup 1.0000x reference)
#include <cuda_runtime.h>

#define NN 50000
#define NE 800000
#define NG 128
#define DD 128
#define NL 4
#define NC 10
#define NT 32   // nodes per tile in the fused layer kernel

// ---------------- device scratch (static: no allocation allowed) ----------------
__device__ float g_hbuf[2][NN * DD];       // ping-pong node features (2 x 25.6 MB)
__device__ int   g_deg[NN];
__device__ int   g_rowptr[NN + 1];
__device__ int   g_cursor[NN];
__device__ int   g_colsrc[NE];
__device__ int   g_gcount[NG];
__device__ int   g_gstart[NG + 1];
__device__ float g_countsf[NG];
__device__ float g_gsum[NG * DD];
__device__ int   g_ei64;                   // 1 if edge_index is int64, else int32
__device__ int   g_b64;                    // 1 if batch is int64, else int32

__device__ __forceinline__ float4 f4add(float4 a, float4 b) {
    a.x += b.x; a.y += b.y; a.z += b.z; a.w += b.w; return a;
}

// ---------------- dtype width detection ----------------
// int64 little-endian nonneg values => every high 32-bit word is zero.
// edge_index: probe first 64 odd words (values random in [0,50000): P(false pos) ~ 0).
// batch (sorted): probe odd words in [20001,20127] — int32 there holds graph ids ~51 (nonzero),
// int64 there holds high halves (zero). All probes stay within the smaller (int32) buffer size.
__global__ void k_detect(const int* __restrict__ ei_w, const int* __restrict__ b_w) {
    if (threadIdx.x == 0 && blockIdx.x == 0) {
        int a = 1;
        for (int i = 0; i < 64; i++) if (ei_w[2 * i + 1] != 0) { a = 0; break; }
        g_ei64 = a;
        int b = 1;
        for (int w = 20001; w < 20129; w += 2) if (b_w[w] != 0) { b = 0; break; }
        g_b64 = b;
    }
}

// ---------------- CSR build ----------------
__global__ void k_zero() {
    int i = blockIdx.x * blockDim.x + threadIdx.x;
    if (i < NN) g_deg[i] = 0;
    if (i < NG) g_gcount[i] = 0;
}

__global__ void k_hist(const void* __restrict__ ei) {
    int e = blockIdx.x * blockDim.x + threadIdx.x;
    if (e < NE) {
        int d = g_ei64 ? (int)((const long long*)ei)[NE + e]
                       : ((const int*)ei)[NE + e];
        atomicAdd(&g_deg[d], 1);
    }
}

__global__ void k_bhist(const void* __restrict__ batch) {
    int i = blockIdx.x * blockDim.x + threadIdx.x;
    if (i < NN) {
        int g = g_b64 ? (int)((const long long*)batch)[i]
                      : ((const int*)batch)[i];
        atomicAdd(&g_gcount[g], 1);
    }
}

__global__ void k_scan() {   // exclusive scan of g_deg -> g_rowptr, copy to g_cursor
    __shared__ int ss[1024];
    int tid = threadIdx.x;
    const int CH = (NN + 1023) / 1024;  // 49
    int base = tid * CH;
    int s = 0;
    for (int i = 0; i < CH; i++) { int idx = base + i; if (idx < NN) s += g_deg[idx]; }
    ss[tid] = s;
    __syncthreads();
    for (int off = 1; off < 1024; off <<= 1) {
        int v = 0;
        if (tid >= off) v = ss[tid - off];
        __syncthreads();
        ss[tid] += v;
        __syncthreads();
    }
    int run = (tid > 0) ? ss[tid - 1] : 0;
    for (int i = 0; i < CH; i++) {
        int idx = base + i;
        if (idx < NN) { g_rowptr[idx] = run; g_cursor[idx] = run; run += g_deg[idx]; }
    }
    if (tid == 1023) g_rowptr[NN] = ss[1023];
}

__global__ void k_fill(const void* __restrict__ ei) {
    int e = blockIdx.x * blockDim.x + threadIdx.x;
    if (e < NE) {
        int s, d;
        if (g_ei64) {
            s = (int)((const long long*)ei)[e];
            d = (int)((const long long*)ei)[NE + e];
        } else {
            s = ((const int*)ei)[e];
            d = ((const int*)ei)[NE + e];
        }
        int p = atomicAdd(&g_cursor[d], 1);
        g_colsrc[p] = s;
    }
}

__global__ void k_gscan() {  // tiny serial scan over 128 graphs
    if (threadIdx.x == 0) {
        int run = 0;
        for (int g = 0; g < NG; g++) {
            g_gstart[g] = run;
            int c = g_gcount[g];
            run += c;
            g_countsf[g] = fmaxf((float)c, 1.f);
        }
        g_gstart[NG] = run;
    }
}

// ---------------- fused layer kernel: agg + MLP1 + MLP2 ----------------
// Persistent: 1 block per SM, W1/W2/biases resident in smem (164864 B dynamic).
// Per tile (32 nodes): Phase A warp-gathers edges (float4 lanes), stage t in smem;
// Phase B1/B2: 256 threads, each owns 4 nodes x 4 dims (16 fp32 accumulators),
// inner k loop = 1 LDS.128 (W row chunk) + 4 broadcast LDS (t) + 16 FFMA -> FMA-bound.
#define SMEM_FLOATS (16384 + 16384 + 128 + 128 + 4096 + 4096)
#define SMEM_BYTES  (SMEM_FLOATS * 4)

__device__ __forceinline__ void gemv_tile(const float* __restrict__ sW,
                                          const float* __restrict__ sIn,
                                          const float* __restrict__ sB,
                                          int lane, int wid, float4 out[4]) {
    float acc[4][4] = {};
    const float4* sW4 = (const float4*)sW;
#pragma unroll 4
    for (int k = 0; k < DD; k++) {
        float4 w = sW4[k * 32 + lane];
        float t0 = sIn[wid * DD + k];
        float t1 = sIn[(wid + 8) * DD + k];
        float t2 = sIn[(wid + 16) * DD + k];
        float t3 = sIn[(wid + 24) * DD + k];
        acc[0][0] += t0 * w.x; acc[0][1] += t0 * w.y; acc[0][2] += t0 * w.z; acc[0][3] += t0 * w.w;
        acc[1][0] += t1 * w.x; acc[1][1] += t1 * w.y; acc[1][2] += t1 * w.z; acc[1][3] += t1 * w.w;
        acc[2][0] += t2 * w.x; acc[2][1] += t2 * w.y; acc[2][2] += t2 * w.z; acc[2][3] += t2 * w.w;
        acc[3][0] += t3 * w.x; acc[3][1] += t3 * w.y; acc[3][2] += t3 * w.z; acc[3][3] += t3 * w.w;
    }
    float4 bb = ((const float4*)sB)[lane];
#pragma unroll
    for (int mi = 0; mi < 4; mi++) {
        out[mi].x = fmaxf(acc[mi][0] + bb.x, 0.f);
        out[mi].y = fmaxf(acc[mi][1] + bb.y, 0.f);
        out[mi].z = fmaxf(acc[mi][2] + bb.z, 0.f);
        out[mi].w = fmaxf(acc[mi][3] + bb.w, 0.f);
    }
}

__global__ void __launch_bounds__(256, 1) k_layer(
    const float* __restrict__ h_in, float* __restrict__ h_out,
    const float* __restrict__ W1, const float* __restrict__ B1,
    const float* __restrict__ W2, const float* __restrict__ B2,
    int numTiles)
{
    extern __shared__ float sm[];
    float* sW1 = sm;                  // 16384
    float* sW2 = sm + 16384;          // 16384
    float* sB1 = sm + 32768;          // 128
    float* sB2 = sm + 32896;          // 128
    float* sT  = sm + 33024;          // 32*128
    float* sY  = sm + 37120;          // 32*128

    int tid = threadIdx.x;
    {   // stage weights once per block (persistent)
        const float4* w14 = (const float4*)W1;
        const float4* w24 = (const float4*)W2;
        float4* s14 = (float4*)sW1;
        float4* s24 = (float4*)sW2;
        for (int i = tid; i < 4096; i += 256) { s14[i] = w14[i]; s24[i] = w24[i]; }
        if (tid < 128) { sB1[tid] = B1[tid]; sB2[tid] = B2[tid]; }
    }
    __syncthreads();

    int lane = tid & 31, wid = tid >> 5;
    const float4* hin4 = (const float4*)h_in;
    float4* hout4 = (float4*)h_out;

    for (int tile = blockIdx.x; tile < numTiles; tile += gridDim.x) {
        // ---- Phase A: (1+eps)*h + sum_{src->n} h[src], staged into sT ----
#pragma unroll 1
        for (int mi = 0; mi < 4; mi++) {
            int m = wid * 4 + mi;
            int n = tile * NT + m;
            float4 t = make_float4(0.f, 0.f, 0.f, 0.f);
            if (n < NN) {
                float4 a0 = t, a1 = t, a2 = t, a3 = t;
                int beg = g_rowptr[n], end = g_rowptr[n + 1];
                int e = beg;
                for (; e + 4 <= end; e += 4) {
                    int s0 = g_colsrc[e], s1 = g_colsrc[e + 1];
                    int s2 = g_colsrc[e + 2], s3 = g_colsrc[e + 3];
                    float4 r0 = __ldg(&hin4[s0 * 32 + lane]);
                    float4 r1 = __ldg(&hin4[s1 * 32 + lane]);
                    float4 r2 = __ldg(&hin4[s2 * 32 + lane]);
                    float4 r3 = __ldg(&hin4[s3 * 32 + lane]);
                    a0 = f4add(a0, r0); a1 = f4add(a1, r1);
                    a2 = f4add(a2, r2); a3 = f4add(a3, r3);
                }
                for (; e < end; e++)
                    a0 = f4add(a0, __ldg(&hin4[g_colsrc[e] * 32 + lane]));
                float4 hh = __ldg(&hin4[n * 32 + lane]);
                t = f4add(f4add(f4add(hh, a0), f4add(a1, a2)), a3);
            }
            ((float4*)sT)[m * 32 + lane] = t;
        }
        __syncthreads();

        // ---- Phase B1: y = relu(t @ W1 + b1) -> sY ----
        float4 y[4];
        gemv_tile(sW1, sT, sB1, lane, wid, y);
#pragma unroll
        for (int mi = 0; mi < 4; mi++)
            ((float4*)sY)[(wid + 8 * mi) * 32 + lane] = y[mi];
        __syncthreads();

        // ---- Phase B2: h_out = relu(y @ W2 + b2) ----
        gemv_tile(sW2, sY, sB2, lane, wid, y);
#pragma unroll
        for (int mi = 0; mi < 4; mi++) {
            int n = tile * NT + wid + 8 * mi;
            if (n < NN) hout4[n * 32 + lane] = y[mi];
        }
        // no trailing sync needed: next Phase A writes sT (not read by B2),
        // and the sync after Phase A orders everything else.
    }
}

// ---------------- GraphNorm (+ trailing relu). batch sorted => contiguous segments ----------------
__global__ void k_gnorm(float* __restrict__ h,
                        const float* __restrict__ w, const float* __restrict__ b,
                        const float* __restrict__ ms) {
    int g = blockIdx.x, d = threadIdx.x;
    int s = g_gstart[g], e = g_gstart[g + 1];
    float cnt = g_countsf[g];
    float sum = 0.f;
    for (int i = s; i < e; i++) sum += h[i * DD + d];
    float mean = (sum / cnt) * ms[d];
    float v = 0.f;
    for (int i = s; i < e; i++) {
        float o = h[i * DD + d] - mean;
        v += o * o;
        h[i * DD + d] = o;
    }
    float inv = rsqrtf(v / cnt + 1e-5f) * w[d];
    float bb = b[d];
    for (int i = s; i < e; i++) {
        float o = h[i * DD + d] * inv + bb;
        h[i * DD + d] = fmaxf(o, 0.f);
    }
}

// ---------------- per-graph sum readout ----------------
__global__ void k_readout(const float* __restrict__ h) {
    int g = blockIdx.x, d = threadIdx.x;
    int s = g_gstart[g], e = g_gstart[g + 1];
    float sum = 0.f;
    for (int i = s; i < e; i++) sum += h[i * DD + d];
    g_gsum[g * DD + d] = sum;
}

// ---------------- head MLP + log_softmax ----------------
__global__ void k_final(const float* __restrict__ fw1, const float* __restrict__ fb1,
                        const float* __restrict__ fw2, const float* __restrict__ fb2,
                        const float* __restrict__ fw3, const float* __restrict__ fb3,
                        float* __restrict__ out) {
    __shared__ float s0[DD], s1[DD], slog[NC], lse;
    int g = blockIdx.x, d = threadIdx.x;
    s0[d] = g_gsum[g * DD + d];
    __syncthreads();
    float a = fb1[d];
#pragma unroll 4
    for (int k = 0; k < DD; k++) a += s0[k] * fw1[k * DD + d];
    s1[d] = fmaxf(a, 0.f);
    __syncthreads();
    float bv = fb2[d];
#pragma unroll 4
    for (int k = 0; k < DD; k++) bv += s1[k] * fw2[k * DD + d];
    s0[d] = fmaxf(bv, 0.f);
    __syncthreads();
    if (d < NC) {
        float c = fb3[d];
        for (int k = 0; k < DD; k++) c += s0[k] * fw3[k * NC + d];
        slog[d] = c;
    }
    __syncthreads();
    if (d == 0) {
        float mx = -1e30f;
        for (int c = 0; c < NC; c++) mx = fmaxf(mx, slog[c]);
        float se = 0.f;
        for (int c = 0; c < NC; c++) se += expf(slog[c] - mx);
        lse = mx + logf(se);
    }
    __syncthreads();
    if (d < NC) out[g * NC + d] = slog[d] - lse;
}

// ---------------- launch ----------------
extern "C" void kernel_launch(void* const* d_in, const int* in_sizes, int n_in,
                              void* d_out, int out_size) {
    const float* x    = (const float*)d_in[0];
    const float* gw1  = (const float*)d_in[1];
    const float* gb1  = (const float*)d_in[2];
    const float* gw2  = (const float*)d_in[3];
    const float* gb2  = (const float*)d_in[4];
    const float* gnw  = (const float*)d_in[5];
    const float* gnb  = (const float*)d_in[6];
    const float* gns  = (const float*)d_in[7];
    const float* fw1  = (const float*)d_in[8];
    const float* fb1  = (const float*)d_in[9];
    const float* fw2  = (const float*)d_in[10];
    const float* fb2  = (const float*)d_in[11];
    const float* fw3  = (const float*)d_in[12];
    const float* fb3  = (const float*)d_in[13];
    const void*  ei   = d_in[14];
    const void*  bat  = d_in[15];
    float* out = (float*)d_out;

    cudaFuncSetAttribute(k_layer, cudaFuncAttributeMaxDynamicSharedMemorySize, SMEM_BYTES);
    int nsm = 148;
    cudaDeviceGetAttribute(&nsm, cudaDevAttrMultiProcessorCount, 0);

    void* p = nullptr;
    cudaGetSymbolAddress(&p, g_hbuf);
    float* hA = (float*)p;
    float* hB = hA + (size_t)NN * DD;

    k_detect<<<1, 32>>>((const int*)ei, (const int*)bat);
    k_zero<<<(NN + 255) / 256, 256>>>();
    k_hist<<<(NE + 255) / 256, 256>>>(ei);
    k_bhist<<<(NN + 255) / 256, 256>>>(bat);
    k_scan<<<1, 1024>>>();
    k_gscan<<<1, 32>>>();
    k_fill<<<(NE + 255) / 256, 256>>>(ei);

    const int numTiles = (NN + NT - 1) / NT;
    const float* cur = x;
    for (int l = 0; l < NL; l++) {
        float* ob = (l & 1) ? hB : hA;  // x->A->B->A->B, never in==out
        k_layer<<<nsm, 256, SMEM_BYTES>>>(cur, ob,
                                          gw1 + l * DD * DD, gb1 + l * DD,
                                          gw2 + l * DD * DD, gb2 + l * DD,
                                          numTiles);
        k_gnorm<<<NG, DD>>>(ob, gnw + l * DD, gnb + l * DD, gns + l * DD);
        cur = ob;
    }
    k_readout<<<NG, DD>>>(cur);
    k_final<<<NG, DD>>>(fw1, fb1, fw2, fb2, fw3, fb3, out);
}

// round 4
// speedup vs baseline: 1.3961x; 1.3961x over previous
#include <cuda_runtime.h>
#include <cuda_bf16.h>

#define NN 50000
#define NE 800000
#define NG 128
#define DD 128
#define NL 4
#define NC 10
#define TM 128
#define NUM_TILES ((NN + TM - 1) / TM)   // 391

// ---------------- device scratch ----------------
__device__ float g_hbuf[2][NN * DD];
__device__ int   g_deg[NN];
__device__ int   g_rowptr[NN + 1];
__device__ int   g_cursor[NN];
__device__ int   g_colsrc[NE];
__device__ int   g_gstart[NG + 1];
__device__ float g_countsf[NG];
__device__ float g_sum[NG * DD];
__device__ float g_sumsq[NG * DD];
__device__ float g_gsum[NG * DD];
__device__ int   g_ei64, g_b64;

// ---------------- helpers ----------------
__device__ __forceinline__ unsigned smem_u32(const void* p) {
    unsigned a;
    asm("{ .reg .u64 t; cvta.to.shared.u64 t, %1; cvt.u32.u64 %0, t; }" : "=r"(a) : "l"(p));
    return a;
}
// swizzled byte offset inside a [128 rows x 256 bytes] bf16 tile
__device__ __forceinline__ unsigned swb(int r, int kb) {
    unsigned w = (unsigned)kb & 127u;
    unsigned sw = w ^ (((unsigned)r & 7u) << 4);
    return (unsigned)r * 256u + ((unsigned)kb & 128u) + sw;
}
__device__ __forceinline__ unsigned pack_bf2(float a, float b) {
    __nv_bfloat162 p = __floats2bfloat162_rn(a, b);
    return *reinterpret_cast<unsigned*>(&p);
}
__device__ __forceinline__ float4 f4add(float4 a, float4 b) {
    a.x += b.x; a.y += b.y; a.z += b.z; a.w += b.w; return a;
}
__device__ __forceinline__ void ldsm4(unsigned* r, unsigned addr) {
    asm volatile("ldmatrix.sync.aligned.m8n8.x4.shared.b16 {%0,%1,%2,%3}, [%4];"
        : "=r"(r[0]), "=r"(r[1]), "=r"(r[2]), "=r"(r[3]) : "r"(addr));
}
__device__ __forceinline__ void ldsm2(unsigned* r, unsigned addr) {
    asm volatile("ldmatrix.sync.aligned.m8n8.x2.shared.b16 {%0,%1}, [%2];"
        : "=r"(r[0]), "=r"(r[1]) : "r"(addr));
}
__device__ __forceinline__ void mma16816(float* d, const unsigned* a, const unsigned* b) {
    asm volatile("mma.sync.aligned.m16n8k16.row.col.f32.bf16.bf16.f32 "
        "{%0,%1,%2,%3}, {%4,%5,%6,%7}, {%8,%9}, {%0,%1,%2,%3};"
        : "+f"(d[0]), "+f"(d[1]), "+f"(d[2]), "+f"(d[3])
        : "r"(a[0]), "r"(a[1]), "r"(a[2]), "r"(a[3]), "r"(b[0]), "r"(b[1]));
}

// ---------------- dtype detection ----------------
__global__ void k_detect(const int* __restrict__ ei_w, const int* __restrict__ b_w) {
    int l = threadIdx.x;
    int ok1 = (ei_w[2 * l + 1] == 0) && (ei_w[2 * (l + 32) + 1] == 0);
    int a = __all_sync(0xffffffffu, ok1);
    int ok2 = (b_w[20001 + 2 * l] == 0) && (b_w[20065 + 2 * l] == 0);
    int b = __all_sync(0xffffffffu, ok2);
    if (l == 0) { g_ei64 = a; g_b64 = b; }
}

// ---------------- CSR build ----------------
__global__ void k_zero() {
    int i = blockIdx.x * blockDim.x + threadIdx.x;
    if (i < NN) g_deg[i] = 0;
}
__global__ void k_hist(const void* __restrict__ ei) {
    int e = blockIdx.x * blockDim.x + threadIdx.x;
    if (e < NE) {
        int d = g_ei64 ? (int)((const long long*)ei)[NE + e] : ((const int*)ei)[NE + e];
        atomicAdd(&g_deg[d], 1);
    }
}
__global__ void k_scan() {
    __shared__ int ss[1024];
    int tid = threadIdx.x;
    const int CH = (NN + 1023) / 1024;
    int base = tid * CH, s = 0;
    for (int i = 0; i < CH; i++) { int idx = base + i; if (idx < NN) s += g_deg[idx]; }
    ss[tid] = s;
    __syncthreads();
    for (int off = 1; off < 1024; off <<= 1) {
        int v = 0;
        if (tid >= off) v = ss[tid - off];
        __syncthreads();
        ss[tid] += v;
        __syncthreads();
    }
    int run = (tid > 0) ? ss[tid - 1] : 0;
    for (int i = 0; i < CH; i++) {
        int idx = base + i;
        if (idx < NN) { g_rowptr[idx] = run; g_cursor[idx] = run; run += g_deg[idx]; }
    }
    if (tid == 1023) g_rowptr[NN] = ss[1023];
}
__global__ void k_fill(const void* __restrict__ ei) {
    int e = blockIdx.x * blockDim.x + threadIdx.x;
    if (e < NE) {
        int s, d;
        if (g_ei64) {
            s = (int)((const long long*)ei)[e];
            d = (int)((const long long*)ei)[NE + e];
        } else {
            s = ((const int*)ei)[e];
            d = ((const int*)ei)[NE + e];
        }
        g_colsrc[atomicAdd(&g_cursor[d], 1)] = s;
    }
}
__global__ void k_gbounds(const void* __restrict__ bat) {
    int g = threadIdx.x;
    long long gg = g;
    int lo = 0, hi = NN;
    while (lo < hi) {
        int mid = (lo + hi) >> 1;
        long long v = g_b64 ? ((const long long*)bat)[mid] : (long long)((const int*)bat)[mid];
        if (v < gg) lo = mid + 1; else hi = mid;
    }
    g_gstart[g] = lo;
    if (g == 0) g_gstart[NG] = NN;
    __syncthreads();
    g_countsf[g] = fmaxf((float)(g_gstart[g + 1] - g_gstart[g]), 1.f);
}

// ---------------- fused layer: gather + bf16x3 mma.sync MLP1 + MLP2 ----------------
#define SM_B1H 0
#define SM_B1L 32768
#define SM_B2H 65536
#define SM_B2L 98304
#define SM_A0  131072
#define SM_A1  163840
#define SM_BI1 196608
#define SM_BI2 197120
#define DYN_SMEM (197632 + 1024)

// One bf16x3 GEMM over the 128x128x128 tile. acc += A @ B (fp32 effective).
__device__ __forceinline__ void gemm_x3(unsigned sbase, unsigned aH, unsigned aL,
                                        unsigned bH, unsigned bL,
                                        int m0, int n0, int lane,
                                        float acc[2][8][4]) {
    int aRow = lane & 15;
    int aKoff = (lane >> 4) * 16;
    int bRow = lane & 7;
    int bKoff = ((lane >> 3) & 1) * 16;
#pragma unroll 1
    for (int ks = 0; ks < 8; ks++) {
        int kb = ks * 32;
        unsigned ah0[4], ah1[4], al0[4], al1[4];
        ldsm4(ah0, sbase + aH + swb(m0 + aRow, kb + aKoff));
        ldsm4(ah1, sbase + aH + swb(m0 + 16 + aRow, kb + aKoff));
        ldsm4(al0, sbase + aL + swb(m0 + aRow, kb + aKoff));
        ldsm4(al1, sbase + aL + swb(m0 + 16 + aRow, kb + aKoff));
#pragma unroll
        for (int nt = 0; nt < 8; nt++) {
            unsigned bh[2], bl[2];
            ldsm2(bh, sbase + bH + swb(n0 + nt * 8 + bRow, kb + bKoff));
            ldsm2(bl, sbase + bL + swb(n0 + nt * 8 + bRow, kb + bKoff));
            mma16816(acc[0][nt], ah0, bh);
            mma16816(acc[1][nt], ah1, bh);
            mma16816(acc[0][nt], al0, bh);
            mma16816(acc[1][nt], al1, bh);
            mma16816(acc[0][nt], ah0, bl);
            mma16816(acc[1][nt], ah1, bl);
        }
    }
}

__global__ void __launch_bounds__(256, 1) k_layer(
    const float* __restrict__ h_in, float* __restrict__ h_out,
    const float* __restrict__ W1, const float* __restrict__ B1,
    const float* __restrict__ W2, const float* __restrict__ B2)
{
    extern __shared__ char smraw[];
    char* sm = (char*)(((unsigned long long)smraw + 1023ull) & ~1023ull);
    unsigned sbase = smem_u32(sm);
    int tid = threadIdx.x, lane = tid & 31, wid = tid >> 5;

    // stage W^T hi/lo (swizzled, Wt[n][k]) + biases. Coalesced LDG; STS scattered (one-time).
    for (int idx = tid; idx < DD * DD; idx += 256) {
        int k = idx >> 7, n = idx & 127;           // consecutive tid -> consecutive n
        float v1 = W1[idx], v2 = W2[idx];          // W[k][n]
        unsigned o = swb(n, 2 * k);
        __nv_bfloat16 h1 = __float2bfloat16(v1), h2 = __float2bfloat16(v2);
        *(__nv_bfloat16*)(sm + SM_B1H + o) = h1;
        *(__nv_bfloat16*)(sm + SM_B1L + o) = __float2bfloat16(v1 - __bfloat162float(h1));
        *(__nv_bfloat16*)(sm + SM_B2H + o) = h2;
        *(__nv_bfloat16*)(sm + SM_B2L + o) = __float2bfloat16(v2 - __bfloat162float(h2));
    }
    if (tid < 128) {
        ((float*)(sm + SM_BI1))[tid] = B1[tid];
        ((float*)(sm + SM_BI2))[tid] = B2[tid];
    }
    __syncthreads();

    const float4* hin4 = (const float4*)h_in;
    const float* bi1 = (const float*)(sm + SM_BI1);
    const float* bi2 = (const float*)(sm + SM_BI2);

    int warpM = wid & 3, warpN = wid >> 2;
    int m0 = warpM * 32, n0 = warpN * 64;
    int r0 = lane >> 2, cq = (lane & 3) * 2;

    for (int tile = blockIdx.x; tile < NUM_TILES; tile += gridDim.x) {
        // ---- gather: 16 nodes per warp; split bf16 hi/lo into swizzled A bufs ----
#pragma unroll 1
        for (int mi = 0; mi < 16; mi++) {
            int m = wid * 16 + mi;
            int n = tile * TM + m;
            float4 t = make_float4(0.f, 0.f, 0.f, 0.f);
            if (n < NN) {
                float4 a0 = t, a1 = t, a2 = t, a3 = t;
                int beg = g_rowptr[n], end = g_rowptr[n + 1];
                int e = beg;
                for (; e + 4 <= end; e += 4) {
                    int s0 = g_colsrc[e], s1 = g_colsrc[e + 1];
                    int s2 = g_colsrc[e + 2], s3 = g_colsrc[e + 3];
                    a0 = f4add(a0, __ldg(&hin4[s0 * 32 + lane]));
                    a1 = f4add(a1, __ldg(&hin4[s1 * 32 + lane]));
                    a2 = f4add(a2, __ldg(&hin4[s2 * 32 + lane]));
                    a3 = f4add(a3, __ldg(&hin4[s3 * 32 + lane]));
                }
                for (; e < end; e++)
                    a0 = f4add(a0, __ldg(&hin4[g_colsrc[e] * 32 + lane]));
                t = f4add(f4add(__ldg(&hin4[n * 32 + lane]), a0), f4add(f4add(a1, a2), a3));
            }
            __nv_bfloat16 hx = __float2bfloat16(t.x), hy = __float2bfloat16(t.y);
            __nv_bfloat16 hz = __float2bfloat16(t.z), hw = __float2bfloat16(t.w);
            unsigned hp0 = pack_bf2(t.x, t.y), hp1 = pack_bf2(t.z, t.w);
            unsigned lp0 = pack_bf2(t.x - __bfloat162float(hx), t.y - __bfloat162float(hy));
            unsigned lp1 = pack_bf2(t.z - __bfloat162float(hz), t.w - __bfloat162float(hw));
            unsigned so = swb(m, lane * 8);   // lane owns k = lane*4..lane*4+3
            *(uint2*)(sm + SM_A0 + so) = make_uint2(hp0, hp1);
            *(uint2*)(sm + SM_A1 + so) = make_uint2(lp0, lp1);
        }
        __syncthreads();

        // ---- MLP1: acc = A @ W1 (bf16x3) ----
        float acc[2][8][4];
#pragma unroll
        for (int a = 0; a < 2; a++)
#pragma unroll
            for (int b = 0; b < 8; b++)
#pragma unroll
                for (int c = 0; c < 4; c++) acc[a][b][c] = 0.f;
        gemm_x3(sbase, SM_A0, SM_A1, SM_B1H, SM_B1L, m0, n0, lane, acc);
        __syncthreads();   // all reads of A done before epilogue overwrites it

        // ---- epilogue 1: bias+relu, re-split into A bufs ----
#pragma unroll
        for (int mt = 0; mt < 2; mt++) {
#pragma unroll
            for (int nt = 0; nt < 8; nt++) {
                int c = n0 + nt * 8 + cq;
                float bb0 = bi1[c], bb1 = bi1[c + 1];
                int mA = m0 + mt * 16 + r0;
                float v0 = fmaxf(acc[mt][nt][0] + bb0, 0.f);
                float v1 = fmaxf(acc[mt][nt][1] + bb1, 0.f);
                float v2 = fmaxf(acc[mt][nt][2] + bb0, 0.f);
                float v3 = fmaxf(acc[mt][nt][3] + bb1, 0.f);
                __nv_bfloat16 h0 = __float2bfloat16(v0), h1 = __float2bfloat16(v1);
                __nv_bfloat16 h2 = __float2bfloat16(v2), h3 = __float2bfloat16(v3);
                unsigned oA = swb(mA, 2 * c), oB = swb(mA + 8, 2 * c);
                *(unsigned*)(sm + SM_A0 + oA) = pack_bf2(v0, v1);
                *(unsigned*)(sm + SM_A1 + oA) =
                    pack_bf2(v0 - __bfloat162float(h0), v1 - __bfloat162float(h1));
                *(unsigned*)(sm + SM_A0 + oB) = pack_bf2(v2, v3);
                *(unsigned*)(sm + SM_A1 + oB) =
                    pack_bf2(v2 - __bfloat162float(h2), v3 - __bfloat162float(h3));
            }
        }
        __syncthreads();

        // ---- MLP2: acc = A @ W2 (bf16x3) ----
#pragma unroll
        for (int a = 0; a < 2; a++)
#pragma unroll
            for (int b = 0; b < 8; b++)
#pragma unroll
                for (int c = 0; c < 4; c++) acc[a][b][c] = 0.f;
        gemm_x3(sbase, SM_A0, SM_A1, SM_B2H, SM_B2L, m0, n0, lane, acc);
        __syncthreads();   // A reads done before next tile's gather overwrites

        // ---- epilogue 2: bias+relu, fp32 to gmem ----
#pragma unroll
        for (int mt = 0; mt < 2; mt++) {
#pragma unroll
            for (int nt = 0; nt < 8; nt++) {
                int c = n0 + nt * 8 + cq;
                float bb0 = bi2[c], bb1 = bi2[c + 1];
                int mA = m0 + mt * 16 + r0;
                int nd0 = tile * TM + mA, nd1 = nd0 + 8;
                if (nd0 < NN) {
                    float2 o;
                    o.x = fmaxf(acc[mt][nt][0] + bb0, 0.f);
                    o.y = fmaxf(acc[mt][nt][1] + bb1, 0.f);
                    *(float2*)(h_out + (size_t)nd0 * DD + c) = o;
                }
                if (nd1 < NN) {
                    float2 o;
                    o.x = fmaxf(acc[mt][nt][2] + bb0, 0.f);
                    o.y = fmaxf(acc[mt][nt][3] + bb1, 0.f);
                    *(float2*)(h_out + (size_t)nd1 * DD + c) = o;
                }
            }
        }
        // no sync needed: epilogue2 touches only gmem + registers
    }
}

// ---------------- GraphNorm: stats pass + normalize pass ----------------
__global__ void k_zstat() {
    int i = blockIdx.x * blockDim.x + threadIdx.x;
    if (i < NG * DD) { g_sum[i] = 0.f; g_sumsq[i] = 0.f; g_gsum[i] = 0.f; }
}
__global__ void k_gstat(const float* __restrict__ h) {
    int g = blockIdx.x, c = blockIdx.y, d = threadIdx.x;
    int s = g_gstart[g], n = g_gstart[g + 1] - s;
    int is = s + (n * c) / 8, ie = s + (n * (c + 1)) / 8;
    float su = 0.f, sq = 0.f;
    for (int i = is; i < ie; i++) {
        float v = h[(size_t)i * DD + d];
        su += v; sq += v * v;
    }
    if (ie > is) {
        atomicAdd(&g_sum[g * DD + d], su);
        atomicAdd(&g_sumsq[g * DD + d], sq);
    }
}
__global__ void k_gnorm2(float* __restrict__ h, const float* __restrict__ w,
                         const float* __restrict__ b, const float* __restrict__ ms,
                         int accum) {
    int g = blockIdx.x, c = blockIdx.y, d = threadIdx.x;
    int s = g_gstart[g], n = g_gstart[g + 1] - s;
    int is = s + (n * c) / 8, ie = s + (n * (c + 1)) / 8;
    float cnt = g_countsf[g];
    float m0 = g_sum[g * DD + d] / cnt;
    float a = m0 * ms[d];
    float var = g_sumsq[g * DD + d] / cnt - 2.f * a * m0 + a * a;
    float inv = rsqrtf(var + 1e-5f) * w[d];
    float bb = b[d];
    float local = 0.f;
    for (int i = is; i < ie; i++) {
        float o = fmaxf((h[(size_t)i * DD + d] - a) * inv + bb, 0.f);
        h[(size_t)i * DD + d] = o;
        local += o;
    }
    if (accum && ie > is) atomicAdd(&g_gsum[g * DD + d], local);
}

// ---------------- head MLP + log_softmax ----------------
__global__ void k_final(const float* __restrict__ fw1, const float* __restrict__ fb1,
                        const float* __restrict__ fw2, const float* __restrict__ fb2,
                        const float* __restrict__ fw3, const float* __restrict__ fb3,
                        float* __restrict__ out) {
    __shared__ float s0[DD], s1[DD], slog[NC], lse;
    int g = blockIdx.x, d = threadIdx.x;
    s0[d] = g_gsum[g * DD + d];
    __syncthreads();
    float a = fb1[d];
#pragma unroll 4
    for (int k = 0; k < DD; k++) a += s0[k] * fw1[k * DD + d];
    s1[d] = fmaxf(a, 0.f);
    __syncthreads();
    float bv = fb2[d];
#pragma unroll 4
    for (int k = 0; k < DD; k++) bv += s1[k] * fw2[k * DD + d];
    s0[d] = fmaxf(bv, 0.f);
    __syncthreads();
    if (d < NC) {
        float c = fb3[d];
        for (int k = 0; k < DD; k++) c += s0[k] * fw3[k * NC + d];
        slog[d] = c;
    }
    __syncthreads();
    if (d == 0) {
        float mx = -1e30f;
        for (int c = 0; c < NC; c++) mx = fmaxf(mx, slog[c]);
        float se = 0.f;
        for (int c = 0; c < NC; c++) se += expf(slog[c] - mx);
        lse = mx + logf(se);
    }
    __syncthreads();
    if (d < NC) out[g * NC + d] = slog[d] - lse;
}

// ---------------- launch ----------------
extern "C" void kernel_launch(void* const* d_in, const int* in_sizes, int n_in,
                              void* d_out, int out_size) {
    const float* x   = (const float*)d_in[0];
    const float* gw1 = (const float*)d_in[1];
    const float* gb1 = (const float*)d_in[2];
    const float* gw2 = (const float*)d_in[3];
    const float* gb2 = (const float*)d_in[4];
    const float* gnw = (const float*)d_in[5];
    const float* gnb = (const float*)d_in[6];
    const float* gns = (const float*)d_in[7];
    const float* fw1 = (const float*)d_in[8];
    const float* fb1 = (const float*)d_in[9];
    const float* fw2 = (const float*)d_in[10];
    const float* fb2 = (const float*)d_in[11];
    const float* fw3 = (const float*)d_in[12];
    const float* fb3 = (const float*)d_in[13];
    const void*  ei  = d_in[14];
    const void*  bat = d_in[15];
    float* out = (float*)d_out;

    cudaFuncSetAttribute(k_layer, cudaFuncAttributeMaxDynamicSharedMemorySize, DYN_SMEM);
    int nsm = 148;
    cudaDeviceGetAttribute(&nsm, cudaDevAttrMultiProcessorCount, 0);

    void* p = nullptr;
    cudaGetSymbolAddress(&p, g_hbuf);
    float* hA = (float*)p;
    float* hB = hA + (size_t)NN * DD;

    k_detect<<<1, 32>>>((const int*)ei, (const int*)bat);
    k_zero<<<(NN + 1023) / 1024, 1024>>>();
    k_hist<<<(NE + 255) / 256, 256>>>(ei);
    k_gbounds<<<1, 128>>>(bat);
    k_scan<<<1, 1024>>>();
    k_fill<<<(NE + 255) / 256, 256>>>(ei);

    const float* cur = x;
    for (int l = 0; l < NL; l++) {
        float* ob = (l & 1) ? hB : hA;
        k_layer<<<nsm, 256, DYN_SMEM>>>(cur, ob,
                                        gw1 + l * DD * DD, gb1 + l * DD,
                                        gw2 + l * DD * DD, gb2 + l * DD);
        k_zstat<<<(NG * DD + 1023) / 1024, 1024>>>();
        k_gstat<<<dim3(NG, 8), DD>>>(ob);
        k_gnorm2<<<dim3(NG, 8), DD>>>(ob, gnw + l * DD, gnb + l * DD, gns + l * DD,
                                      (l == NL - 1) ? 1 : 0);
        cur = ob;
    }
    k_final<<<NG, DD>>>(fw1, fb1, fw2, fb2, fw3, fb3, out);
}

// round 5
// speedup vs baseline: 1.5003x; 1.0747x over previous
#include <cuda_runtime.h>
#include <cuda_bf16.h>

#define NN 50000
#define NE 800000
#define NG 128
#define DD 128
#define NL 4
#define NC 10
#define TM 128
#define NUM_TILES ((NN + TM - 1) / TM)   // 391

// ---------------- device scratch ----------------
__device__ float g_hbuf[2][NN * DD];
__device__ int   g_deg[NN];
__device__ int   g_rowptr[NN + 1];
__device__ int   g_cursor[NN];
__device__ int   g_colsrc[NE];
__device__ int   g_gstart[NG + 1];
__device__ int   g_nodeg[NN];
__device__ float g_countsf[NG];
__device__ float g_sum2[2][NG * DD];
__device__ float g_sumsq2[2][NG * DD];
__device__ float g_gsum[NG * DD];
__device__ int   g_tilectr[NL];
__device__ int   g_ei64, g_b64;

// ---------------- helpers ----------------
__device__ __forceinline__ unsigned smem_u32(const void* p) {
    unsigned a;
    asm("{ .reg .u64 t; cvta.to.shared.u64 t, %1; cvt.u32.u64 %0, t; }" : "=r"(a) : "l"(p));
    return a;
}
// swizzled byte offset inside a [128 rows x 256 bytes] bf16 tile
__device__ __forceinline__ unsigned swb(int r, int kb) {
    unsigned w = (unsigned)kb & 127u;
    unsigned sw = w ^ (((unsigned)r & 7u) << 4);
    return (unsigned)r * 256u + ((unsigned)kb & 128u) + sw;
}
__device__ __forceinline__ unsigned pack_bf2(float a, float b) {
    __nv_bfloat162 p = __floats2bfloat162_rn(a, b);
    return *reinterpret_cast<unsigned*>(&p);
}
__device__ __forceinline__ float4 f4add(float4 a, float4 b) {
    a.x += b.x; a.y += b.y; a.z += b.z; a.w += b.w; return a;
}
__device__ __forceinline__ void ldsm4(unsigned* r, unsigned addr) {
    asm volatile("ldmatrix.sync.aligned.m8n8.x4.shared.b16 {%0,%1,%2,%3}, [%4];"
        : "=r"(r[0]), "=r"(r[1]), "=r"(r[2]), "=r"(r[3]) : "r"(addr));
}
__device__ __forceinline__ void ldsm2(unsigned* r, unsigned addr) {
    asm volatile("ldmatrix.sync.aligned.m8n8.x2.shared.b16 {%0,%1}, [%2];"
        : "=r"(r[0]), "=r"(r[1]) : "r"(addr));
}
__device__ __forceinline__ void mma16816(float* d, const unsigned* a, const unsigned* b) {
    asm volatile("mma.sync.aligned.m16n8k16.row.col.f32.bf16.bf16.f32 "
        "{%0,%1,%2,%3}, {%4,%5,%6,%7}, {%8,%9}, {%0,%1,%2,%3};"
        : "+f"(d[0]), "+f"(d[1]), "+f"(d[2]), "+f"(d[3])
        : "r"(a[0]), "r"(a[1]), "r"(a[2]), "r"(a[3]), "r"(b[0]), "r"(b[1]));
}

// ---------------- dtype detection ----------------
__global__ void k_detect(const int* __restrict__ ei_w, const int* __restrict__ b_w) {
    int l = threadIdx.x;
    int ok1 = (ei_w[2 * l + 1] == 0) && (ei_w[2 * (l + 32) + 1] == 0);
    int a = __all_sync(0xffffffffu, ok1);
    int ok2 = (b_w[20001 + 2 * l] == 0) && (b_w[20065 + 2 * l] == 0);
    int b = __all_sync(0xffffffffu, ok2);
    if (l == 0) { g_ei64 = a; g_b64 = b; }
}

// ---------------- init: zero everything resettable ----------------
__global__ void k_init() {
    int i = blockIdx.x * blockDim.x + threadIdx.x;
    if (i < NN) g_deg[i] = 0;
    if (i < NG * DD) {
        g_sum2[0][i] = 0.f; g_sum2[1][i] = 0.f;
        g_sumsq2[0][i] = 0.f; g_sumsq2[1][i] = 0.f;
        g_gsum[i] = 0.f;
    }
    if (i < NL) g_tilectr[i] = 0;
}

// ---------------- graph bounds + node->graph (parallel boundary detect) ----------------
__global__ void k_gbounds(const void* __restrict__ bat) {
    int i = blockIdx.x * blockDim.x + threadIdx.x;
    if (i >= NN) return;
    int bi = g_b64 ? (int)((const long long*)bat)[i] : ((const int*)bat)[i];
    g_nodeg[i] = bi;
    int prev = -1;
    if (i > 0)
        prev = g_b64 ? (int)((const long long*)bat)[i - 1] : ((const int*)bat)[i - 1];
    for (int g = prev + 1; g <= bi; g++) g_gstart[g] = i;
    if (i == NN - 1)
        for (int g = bi + 1; g <= NG; g++) g_gstart[g] = NN;
}

// ---------------- CSR build ----------------
__global__ void k_hist(const void* __restrict__ ei) {
    int e = blockIdx.x * blockDim.x + threadIdx.x;
    if (e < NE) {
        int d = g_ei64 ? (int)((const long long*)ei)[NE + e] : ((const int*)ei)[NE + e];
        atomicAdd(&g_deg[d], 1);
    }
}
__global__ void k_scan() {
    __shared__ int ss[1024];
    int tid = threadIdx.x;
    if (tid < NG)
        g_countsf[tid] = fmaxf((float)(g_gstart[tid + 1] - g_gstart[tid]), 1.f);
    const int CH = (NN + 1023) / 1024;
    int base = tid * CH, s = 0;
    for (int i = 0; i < CH; i++) { int idx = base + i; if (idx < NN) s += g_deg[idx]; }
    ss[tid] = s;
    __syncthreads();
    for (int off = 1; off < 1024; off <<= 1) {
        int v = 0;
        if (tid >= off) v = ss[tid - off];
        __syncthreads();
        ss[tid] += v;
        __syncthreads();
    }
    int run = (tid > 0) ? ss[tid - 1] : 0;
    for (int i = 0; i < CH; i++) {
        int idx = base + i;
        if (idx < NN) { g_rowptr[idx] = run; g_cursor[idx] = run; run += g_deg[idx]; }
    }
    if (tid == 1023) g_rowptr[NN] = ss[1023];
}
__global__ void k_fill(const void* __restrict__ ei) {
    int e = blockIdx.x * blockDim.x + threadIdx.x;
    if (e < NE) {
        int s, d;
        if (g_ei64) {
            s = (int)((const long long*)ei)[e];
            d = (int)((const long long*)ei)[NE + e];
        } else {
            s = ((const int*)ei)[e];
            d = ((const int*)ei)[NE + e];
        }
        g_colsrc[atomicAdd(&g_cursor[d], 1)] = s;
    }
}

// ---------------- fused layer: gather + bf16x3 mma.sync MLP1+MLP2 + GN stats ----------------
#define SM_B1H 0
#define SM_B1L 32768
#define SM_B2H 65536
#define SM_B2L 98304
#define SM_A0  131072
#define SM_A1  163840
#define SM_BI1 196608
#define SM_BI2 197120
#define DYN_SMEM (197632 + 1024)

__device__ __forceinline__ void gemm_x3(unsigned sbase, unsigned aH, unsigned aL,
                                        unsigned bH, unsigned bL,
                                        int m0, int n0, int lane,
                                        float acc[2][8][4]) {
    int aRow = lane & 15;
    int aKoff = (lane >> 4) * 16;
    int bRow = lane & 7;
    int bKoff = ((lane >> 3) & 1) * 16;
#pragma unroll 1
    for (int ks = 0; ks < 8; ks++) {
        int kb = ks * 32;
        unsigned ah0[4], ah1[4], al0[4], al1[4];
        ldsm4(ah0, sbase + aH + swb(m0 + aRow, kb + aKoff));
        ldsm4(ah1, sbase + aH + swb(m0 + 16 + aRow, kb + aKoff));
        ldsm4(al0, sbase + aL + swb(m0 + aRow, kb + aKoff));
        ldsm4(al1, sbase + aL + swb(m0 + 16 + aRow, kb + aKoff));
#pragma unroll
        for (int nt = 0; nt < 8; nt++) {
            unsigned bh[2], bl[2];
            ldsm2(bh, sbase + bH + swb(n0 + nt * 8 + bRow, kb + bKoff));
            ldsm2(bl, sbase + bL + swb(n0 + nt * 8 + bRow, kb + bKoff));
            mma16816(acc[0][nt], ah0, bh);
            mma16816(acc[1][nt], ah1, bh);
            mma16816(acc[0][nt], al0, bh);
            mma16816(acc[1][nt], al1, bh);
            mma16816(acc[0][nt], ah0, bl);
            mma16816(acc[1][nt], ah1, bl);
        }
    }
}

__global__ void __launch_bounds__(256, 1) k_layer(
    const float* __restrict__ h_in, float* __restrict__ h_out,
    const float* __restrict__ W1, const float* __restrict__ B1,
    const float* __restrict__ W2, const float* __restrict__ B2,
    int layer)
{
    extern __shared__ char smraw[];
    char* sm = (char*)(((unsigned long long)smraw + 1023ull) & ~1023ull);
    unsigned sbase = smem_u32(sm);
    __shared__ int s_tile;
    int tid = threadIdx.x, lane = tid & 31, wid = tid >> 5;
    int par = layer & 1;

    // stage W^T hi/lo (swizzled) + biases
    for (int idx = tid; idx < DD * DD; idx += 256) {
        int k = idx >> 7, n = idx & 127;
        float v1 = W1[idx], v2 = W2[idx];
        unsigned o = swb(n, 2 * k);
        __nv_bfloat16 h1 = __float2bfloat16(v1), h2 = __float2bfloat16(v2);
        *(__nv_bfloat16*)(sm + SM_B1H + o) = h1;
        *(__nv_bfloat16*)(sm + SM_B1L + o) = __float2bfloat16(v1 - __bfloat162float(h1));
        *(__nv_bfloat16*)(sm + SM_B2H + o) = h2;
        *(__nv_bfloat16*)(sm + SM_B2L + o) = __float2bfloat16(v2 - __bfloat162float(h2));
    }
    if (tid < 128) {
        ((float*)(sm + SM_BI1))[tid] = B1[tid];
        ((float*)(sm + SM_BI2))[tid] = B2[tid];
    }
    __syncthreads();

    const float4* hin4 = (const float4*)h_in;
    const float* bi1 = (const float*)(sm + SM_BI1);
    const float* bi2 = (const float*)(sm + SM_BI2);

    int warpM = wid & 3, warpN = wid >> 2;
    int m0 = warpM * 32, n0 = warpN * 64;
    int r0 = lane >> 2, cq = (lane & 3) * 2;

    for (;;) {
        if (tid == 0) s_tile = atomicAdd(&g_tilectr[layer], 1);
        __syncthreads();
        int tile = s_tile;
        if (tile >= NUM_TILES) break;

        // ---- gather: 16 nodes/warp, 8 float4 loads in flight ----
#pragma unroll 1
        for (int mi = 0; mi < 16; mi++) {
            int m = wid * 16 + mi;
            int n = tile * TM + m;
            float4 t = make_float4(0.f, 0.f, 0.f, 0.f);
            if (n < NN) {
                float4 a0 = t, a1 = t, a2 = t, a3 = t, a4 = t, a5 = t, a6 = t, a7 = t;
                int beg = g_rowptr[n], end = g_rowptr[n + 1];
                int e = beg;
                for (; e + 8 <= end; e += 8) {
                    int s0 = g_colsrc[e],     s1 = g_colsrc[e + 1];
                    int s2 = g_colsrc[e + 2], s3 = g_colsrc[e + 3];
                    int s4 = g_colsrc[e + 4], s5 = g_colsrc[e + 5];
                    int s6 = g_colsrc[e + 6], s7 = g_colsrc[e + 7];
                    a0 = f4add(a0, __ldg(&hin4[s0 * 32 + lane]));
                    a1 = f4add(a1, __ldg(&hin4[s1 * 32 + lane]));
                    a2 = f4add(a2, __ldg(&hin4[s2 * 32 + lane]));
                    a3 = f4add(a3, __ldg(&hin4[s3 * 32 + lane]));
                    a4 = f4add(a4, __ldg(&hin4[s4 * 32 + lane]));
                    a5 = f4add(a5, __ldg(&hin4[s5 * 32 + lane]));
                    a6 = f4add(a6, __ldg(&hin4[s6 * 32 + lane]));
                    a7 = f4add(a7, __ldg(&hin4[s7 * 32 + lane]));
                }
                if (e + 4 <= end) {
                    int s0 = g_colsrc[e],     s1 = g_colsrc[e + 1];
                    int s2 = g_colsrc[e + 2], s3 = g_colsrc[e + 3];
                    a0 = f4add(a0, __ldg(&hin4[s0 * 32 + lane]));
                    a1 = f4add(a1, __ldg(&hin4[s1 * 32 + lane]));
                    a2 = f4add(a2, __ldg(&hin4[s2 * 32 + lane]));
                    a3 = f4add(a3, __ldg(&hin4[s3 * 32 + lane]));
                    e += 4;
                }
                for (; e < end; e++)
                    a0 = f4add(a0, __ldg(&hin4[g_colsrc[e] * 32 + lane]));
                float4 s01 = f4add(f4add(a0, a1), f4add(a2, a3));
                float4 s23 = f4add(f4add(a4, a5), f4add(a6, a7));
                t = f4add(f4add(__ldg(&hin4[n * 32 + lane]), s01), s23);
            }
            __nv_bfloat16 hx = __float2bfloat16(t.x), hy = __float2bfloat16(t.y);
            __nv_bfloat16 hz = __float2bfloat16(t.z), hw = __float2bfloat16(t.w);
            unsigned hp0 = pack_bf2(t.x, t.y), hp1 = pack_bf2(t.z, t.w);
            unsigned lp0 = pack_bf2(t.x - __bfloat162float(hx), t.y - __bfloat162float(hy));
            unsigned lp1 = pack_bf2(t.z - __bfloat162float(hz), t.w - __bfloat162float(hw));
            unsigned so = swb(m, lane * 8);
            *(uint2*)(sm + SM_A0 + so) = make_uint2(hp0, hp1);
            *(uint2*)(sm + SM_A1 + so) = make_uint2(lp0, lp1);
        }
        __syncthreads();

        // ---- MLP1 ----
        float acc[2][8][4];
#pragma unroll
        for (int a = 0; a < 2; a++)
#pragma unroll
            for (int b = 0; b < 8; b++)
#pragma unroll
                for (int c = 0; c < 4; c++) acc[a][b][c] = 0.f;
        gemm_x3(sbase, SM_A0, SM_A1, SM_B1H, SM_B1L, m0, n0, lane, acc);
        __syncthreads();

        // ---- epilogue 1: bias+relu, re-split into A ----
#pragma unroll
        for (int mt = 0; mt < 2; mt++) {
#pragma unroll
            for (int nt = 0; nt < 8; nt++) {
                int c = n0 + nt * 8 + cq;
                float bb0 = bi1[c], bb1 = bi1[c + 1];
                int mA = m0 + mt * 16 + r0;
                float v0 = fmaxf(acc[mt][nt][0] + bb0, 0.f);
                float v1 = fmaxf(acc[mt][nt][1] + bb1, 0.f);
                float v2 = fmaxf(acc[mt][nt][2] + bb0, 0.f);
                float v3 = fmaxf(acc[mt][nt][3] + bb1, 0.f);
                __nv_bfloat16 h0 = __float2bfloat16(v0), h1 = __float2bfloat16(v1);
                __nv_bfloat16 h2 = __float2bfloat16(v2), h3 = __float2bfloat16(v3);
                unsigned oA = swb(mA, 2 * c), oB = swb(mA + 8, 2 * c);
                *(unsigned*)(sm + SM_A0 + oA) = pack_bf2(v0, v1);
                *(unsigned*)(sm + SM_A1 + oA) =
                    pack_bf2(v0 - __bfloat162float(h0), v1 - __bfloat162float(h1));
                *(unsigned*)(sm + SM_A0 + oB) = pack_bf2(v2, v3);
                *(unsigned*)(sm + SM_A1 + oB) =
                    pack_bf2(v2 - __bfloat162float(h2), v3 - __bfloat162float(h3));
            }
        }
        __syncthreads();

        // ---- MLP2 ----
#pragma unroll
        for (int a = 0; a < 2; a++)
#pragma unroll
            for (int b = 0; b < 8; b++)
#pragma unroll
                for (int c = 0; c < 4; c++) acc[a][b][c] = 0.f;
        gemm_x3(sbase, SM_A0, SM_A1, SM_B2H, SM_B2L, m0, n0, lane, acc);
        __syncthreads();

        // ---- epilogue 2: bias+relu -> gmem; keep values in acc for stats ----
#pragma unroll
        for (int mt = 0; mt < 2; mt++) {
#pragma unroll
            for (int nt = 0; nt < 8; nt++) {
                int c = n0 + nt * 8 + cq;
                float bb0 = bi2[c], bb1 = bi2[c + 1];
                int mA = m0 + mt * 16 + r0;
                int nd0 = tile * TM + mA, nd1 = nd0 + 8;
                float o0 = fmaxf(acc[mt][nt][0] + bb0, 0.f);
                float o1 = fmaxf(acc[mt][nt][1] + bb1, 0.f);
                float o2 = fmaxf(acc[mt][nt][2] + bb0, 0.f);
                float o3 = fmaxf(acc[mt][nt][3] + bb1, 0.f);
                acc[mt][nt][0] = o0; acc[mt][nt][1] = o1;
                acc[mt][nt][2] = o2; acc[mt][nt][3] = o3;
                if (nd0 < NN) *(float2*)(h_out + (size_t)nd0 * DD + c) = make_float2(o0, o1);
                if (nd1 < NN) *(float2*)(h_out + (size_t)nd1 * DD + c) = make_float2(o2, o3);
            }
        }

        // ---- fused GraphNorm stats: per-tile column reduce + atomics ----
        {
            int base = tile * TM;
            int gs = g_nodeg[base];
            int lastn = base + TM - 1; if (lastn >= NN) lastn = NN - 1;
            int ge = g_nodeg[lastn];
            int rb[4];
#pragma unroll
            for (int j = 0; j < 4; j++) {
                int nd = base + m0 + j * 8 + r0;
                rb[j] = (nd < NN) ? g_nodeg[nd] : -1;
            }
            float* scrS = (float*)(sm + SM_A0);        // 4*128 floats
            float* scrQ = scrS + 512;                  // 4*128 floats
            for (int g = gs; g <= ge; g++) {
                float pv[16], qv[16];
#pragma unroll
                for (int nt = 0; nt < 8; nt++) {
                    float p0 = 0.f, p1 = 0.f, q0 = 0.f, q1 = 0.f;
#pragma unroll
                    for (int mt = 0; mt < 2; mt++) {
                        if (rb[mt * 2 + 0] == g) {
                            float v0 = acc[mt][nt][0], v1 = acc[mt][nt][1];
                            p0 += v0; q0 += v0 * v0; p1 += v1; q1 += v1 * v1;
                        }
                        if (rb[mt * 2 + 1] == g) {
                            float v0 = acc[mt][nt][2], v1 = acc[mt][nt][3];
                            p0 += v0; q0 += v0 * v0; p1 += v1; q1 += v1 * v1;
                        }
                    }
                    pv[nt * 2] = p0; pv[nt * 2 + 1] = p1;
                    qv[nt * 2] = q0; qv[nt * 2 + 1] = q1;
                }
#pragma unroll
                for (int k = 0; k < 16; k++) {
#pragma unroll
                    for (int o = 4; o <= 16; o <<= 1) {
                        pv[k] += __shfl_xor_sync(0xffffffffu, pv[k], o);
                        qv[k] += __shfl_xor_sync(0xffffffffu, qv[k], o);
                    }
                }
                if (r0 == 0) {
#pragma unroll
                    for (int nt = 0; nt < 8; nt++) {
                        int c = n0 + nt * 8 + cq;
                        scrS[warpM * 128 + c]     = pv[nt * 2];
                        scrS[warpM * 128 + c + 1] = pv[nt * 2 + 1];
                        scrQ[warpM * 128 + c]     = qv[nt * 2];
                        scrQ[warpM * 128 + c + 1] = qv[nt * 2 + 1];
                    }
                }
                __syncthreads();
                if (tid < 128) {
                    float s = scrS[tid] + scrS[128 + tid] + scrS[256 + tid] + scrS[384 + tid];
                    atomicAdd(&g_sum2[par][g * DD + tid], s);
                } else {
                    int d2 = tid - 128;
                    float s = scrQ[d2] + scrQ[128 + d2] + scrQ[256 + d2] + scrQ[384 + d2];
                    atomicAdd(&g_sumsq2[par][g * DD + d2], s);
                }
                __syncthreads();
            }
        }
    }
}

// ---------------- GraphNorm normalize (+zero next-parity stats, +readout) ----------------
__global__ void k_gnorm2(float* __restrict__ h, const float* __restrict__ w,
                         const float* __restrict__ b, const float* __restrict__ ms,
                         int layer) {
    int par = layer & 1;
    int g = blockIdx.x, c = blockIdx.y, d = threadIdx.x;
    int s = g_gstart[g], n = g_gstart[g + 1] - s;
    int is = s + (n * c) / 8, ie = s + (n * (c + 1)) / 8;
    float cnt = g_countsf[g];
    float m0 = g_sum2[par][g * DD + d] / cnt;
    float a = m0 * ms[d];
    float var = g_sumsq2[par][g * DD + d] / cnt - 2.f * a * m0 + a * a;
    float inv = rsqrtf(var + 1e-5f) * w[d];
    float bb = b[d];
    // zero next-parity stats for the next layer (benign redundant writes)
    g_sum2[par ^ 1][g * DD + d] = 0.f;
    g_sumsq2[par ^ 1][g * DD + d] = 0.f;
    float local = 0.f;
    for (int i = is; i < ie; i++) {
        float o = fmaxf((h[(size_t)i * DD + d] - a) * inv + bb, 0.f);
        h[(size_t)i * DD + d] = o;
        local += o;
    }
    if (layer == NL - 1 && ie > is) atomicAdd(&g_gsum[g * DD + d], local);
}

// ---------------- head MLP + log_softmax ----------------
__global__ void k_final(const float* __restrict__ fw1, const float* __restrict__ fb1,
                        const float* __restrict__ fw2, const float* __restrict__ fb2,
                        const float* __restrict__ fw3, const float* __restrict__ fb3,
                        float* __restrict__ out) {
    __shared__ float s0[DD], s1[DD], slog[NC], lse;
    int g = blockIdx.x, d = threadIdx.x;
    s0[d] = g_gsum[g * DD + d];
    __syncthreads();
    float a = fb1[d];
#pragma unroll 4
    for (int k = 0; k < DD; k++) a += s0[k] * fw1[k * DD + d];
    s1[d] = fmaxf(a, 0.f);
    __syncthreads();
    float bv = fb2[d];
#pragma unroll 4
    for (int k = 0; k < DD; k++) bv += s1[k] * fw2[k * DD + d];
    s0[d] = fmaxf(bv, 0.f);
    __syncthreads();
    if (d < NC) {
        float c = fb3[d];
        for (int k = 0; k < DD; k++) c += s0[k] * fw3[k * NC + d];
        slog[d] = c;
    }
    __syncthreads();
    if (d == 0) {
        float mx = -1e30f;
        for (int c = 0; c < NC; c++) mx = fmaxf(mx, slog[c]);
        float se = 0.f;
        for (int c = 0; c < NC; c++) se += expf(slog[c] - mx);
        lse = mx + logf(se);
    }
    __syncthreads();
    if (d < NC) out[g * NC + d] = slog[d] - lse;
}

// ---------------- launch ----------------
extern "C" void kernel_launch(void* const* d_in, const int* in_sizes, int n_in,
                              void* d_out, int out_size) {
    const float* x   = (const float*)d_in[0];
    const float* gw1 = (const float*)d_in[1];
    const float* gb1 = (const float*)d_in[2];
    const float* gw2 = (const float*)d_in[3];
    const float* gb2 = (const float*)d_in[4];
    const float* gnw = (const float*)d_in[5];
    const float* gnb = (const float*)d_in[6];
    const float* gns = (const float*)d_in[7];
    const float* fw1 = (const float*)d_in[8];
    const float* fb1 = (const float*)d_in[9];
    const float* fw2 = (const float*)d_in[10];
    const float* fb2 = (const float*)d_in[11];
    const float* fw3 = (const float*)d_in[12];
    const float* fb3 = (const float*)d_in[13];
    const void*  ei  = d_in[14];
    const void*  bat = d_in[15];
    float* out = (float*)d_out;

    cudaFuncSetAttribute(k_layer, cudaFuncAttributeMaxDynamicSharedMemorySize, DYN_SMEM);
    int nsm = 148;
    cudaDeviceGetAttribute(&nsm, cudaDevAttrMultiProcessorCount, 0);

    void* p = nullptr;
    cudaGetSymbolAddress(&p, g_hbuf);
    float* hA = (float*)p;
    float* hB = hA + (size_t)NN * DD;

    k_detect<<<1, 32>>>((const int*)ei, (const int*)bat);
    k_init<<<(NN + 1023) / 1024, 1024>>>();
    k_gbounds<<<(NN + 255) / 256, 256>>>(bat);
    k_hist<<<(NE + 255) / 256, 256>>>(ei);
    k_scan<<<1, 1024>>>();
    k_fill<<<(NE + 255) / 256, 256>>>(ei);

    const float* cur = x;
    for (int l = 0; l < NL; l++) {
        float* ob = (l & 1) ? hB : hA;
        k_layer<<<nsm, 256, DYN_SMEM>>>(cur, ob,
                                        gw1 + l * DD * DD, gb1 + l * DD,
                                        gw2 + l * DD * DD, gb2 + l * DD, l);
        k_gnorm2<<<dim3(NG, 8), DD>>>(ob, gnw + l * DD, gnb + l * DD, gns + l * DD, l);
        cur = ob;
    }
    k_final<<<NG, DD>>>(fw1, fb1, fw2, fb2, fw3, fb3, out);
}